// round 2
// baseline (speedup 1.0000x reference)
#include <cuda_runtime.h>

#define N_NODES 16384
#define N_EDGES 524288
#define HID 256
#define HHALF 128
#define R2 2500.0f
#define EPSV 1e-8f
#define NPB 32   // nodes per block in MLP kernel

// ---------------- scratch (device globals: no allocation allowed) ----------
__device__ int   g_deg[N_NODES];
__device__ int   g_fill[N_NODES];
__device__ int   g_csr_ptr[N_NODES + 1];
__device__ int   g_csr_col[N_EDGES];
__device__ float g_density[N_NODES];   // raw in-radius count (incl. self)
__device__ float g_fvar[N_NODES];
__device__ float g_max[4];             // [0]=max deg, [1]=max density, [2]=max fvar

// ---------------- init -----------------------------------------------------
__global__ void k_zero() {
    int i = blockIdx.x * blockDim.x + threadIdx.x;
    if (i < N_NODES) { g_deg[i] = 0; g_fill[i] = 0; g_density[i] = 0.0f; }
    if (i < 4) g_max[i] = 0.0f;
}

// ---------------- degree ---------------------------------------------------
__global__ void k_degree(const int* __restrict__ row) {
    int e = blockIdx.x * blockDim.x + threadIdx.x;
    if (e < N_EDGES) atomicAdd(&g_deg[row[e]], 1);
}

// ---------------- exclusive scan of degrees (single block, 1024 thr) -------
__global__ void k_scan() {
    __shared__ int s[1024];
    int t = threadIdx.x;
    int base = t * 16;
    int loc[16];
    int sum = 0;
#pragma unroll
    for (int k = 0; k < 16; k++) { loc[k] = sum; sum += g_deg[base + k]; }
    s[t] = sum;
    __syncthreads();
    // Hillis-Steele inclusive scan over 1024 partials
    for (int off = 1; off < 1024; off <<= 1) {
        int v = (t >= off) ? s[t - off] : 0;
        __syncthreads();
        s[t] += v;
        __syncthreads();
    }
    int excl = (t == 0) ? 0 : s[t - 1];
#pragma unroll
    for (int k = 0; k < 16; k++) g_csr_ptr[base + k] = excl + loc[k];
    if (t == 1023) g_csr_ptr[N_NODES] = s[1023];
}

// ---------------- CSR fill -------------------------------------------------
__global__ void k_fill(const int* __restrict__ row, const int* __restrict__ col) {
    int e = blockIdx.x * blockDim.x + threadIdx.x;
    if (e < N_EDGES) {
        int r = row[e];
        int pos = g_csr_ptr[r] + atomicAdd(&g_fill[r], 1);
        g_csr_col[pos] = col[e];
    }
}

// ---------------- spatial density (brute-force N^2, tiled) -----------------
// grid: (64, 8) blocks of 256 threads. block.x -> 256 i's, block.y -> 2048 j's
__global__ void k_density(const float2* __restrict__ coords) {
    __shared__ float2 sc[256];
    int i = blockIdx.x * 256 + threadIdx.x;
    float2 p = coords[i];
    int j0 = blockIdx.y * 2048;
    int cnt = 0;
    for (int tile = 0; tile < 2048; tile += 256) {
        sc[threadIdx.x] = coords[j0 + tile + threadIdx.x];
        __syncthreads();
#pragma unroll 32
        for (int k = 0; k < 256; k++) {
            float dx = p.x - sc[k].x;
            float dy = p.y - sc[k].y;
            float d2 = fmaf(dx, dx, dy * dy);
            cnt += (d2 <= R2) ? 1 : 0;
        }
        __syncthreads();
    }
    atomicAdd(&g_density[i], (float)cnt);   // integer-valued: order-independent exact
}

// ---------------- local feature variance (block per node) ------------------
__global__ void k_fvar(const float* __restrict__ x) {
    int n = blockIdx.x;
    int h = threadIdx.x;            // 256 threads: one per feature
    int beg = g_csr_ptr[n], end = g_csr_ptr[n + 1];

    float s0 = 0.f, s1 = 0.f, s2 = 0.f, s3 = 0.f;
    int e = beg;
    for (; e + 4 <= end; e += 4) {
        int c0 = g_csr_col[e];
        int c1 = g_csr_col[e + 1];
        int c2 = g_csr_col[e + 2];
        int c3 = g_csr_col[e + 3];
        s0 += x[c0 * HID + h];
        s1 += x[c1 * HID + h];
        s2 += x[c2 * HID + h];
        s3 += x[c3 * HID + h];
    }
    for (; e < end; e++) s0 += x[g_csr_col[e] * HID + h];
    float s = (s0 + s1) + (s2 + s3);

    float cnt = (float)((end - beg) > 1 ? (end - beg) : 1);
    float d = x[n * HID + h] - s / cnt;

    __shared__ float red[256];
    red[h] = d * d;
    __syncthreads();
    for (int off = 128; off > 0; off >>= 1) {
        if (h < off) red[h] += red[h + off];
        __syncthreads();
    }
    if (h == 0) g_fvar[n] = sqrtf(red[0]);
}

// ---------------- maxima reduction -----------------------------------------
__global__ void k_max() {
    __shared__ float m0[1024], m1[1024], m2[1024];
    int t = threadIdx.x;
    float a = 0.f, b = 0.f, c = 0.f;
    for (int i = t; i < N_NODES; i += 1024) {
        a = fmaxf(a, (float)g_deg[i]);
        b = fmaxf(b, g_density[i] - 1.0f);
        c = fmaxf(c, g_fvar[i]);
    }
    m0[t] = a; m1[t] = b; m2[t] = c;
    __syncthreads();
    for (int off = 512; off > 0; off >>= 1) {
        if (t < off) {
            m0[t] = fmaxf(m0[t], m0[t + off]);
            m1[t] = fmaxf(m1[t], m1[t + off]);
            m2[t] = fmaxf(m2[t], m2[t + off]);
        }
        __syncthreads();
    }
    if (t == 0) { g_max[0] = m0[0]; g_max[1] = m1[0]; g_max[2] = m2[0]; }
}

// ---------------- MLP: 32 nodes per block, 256 output cols -----------------
__global__ void k_mlp(const float* __restrict__ w1, const float* __restrict__ b1,
                      const float* __restrict__ w2, const float* __restrict__ b2,
                      float* __restrict__ out) {
    __shared__ float feats[NPB][3];
    __shared__ __align__(16) float hid[HHALF][NPB];   // transposed: [j][node]
    int t = threadIdx.x;
    int n0 = blockIdx.x * NPB;

    if (t < NPB) {
        int n = n0 + t;
        float invd   = 1.0f / (g_max[0] + EPSV);
        float invden = 1.0f / (g_max[1] + EPSV);
        float invf   = 1.0f / (g_max[2] + EPSV);
        feats[t][0] = (float)g_deg[n] * invd;
        feats[t][1] = (g_density[n] - 1.0f) * invden;
        feats[t][2] = g_fvar[n] * invf;
    }
    __syncthreads();

    // hidden layer: 32 nodes x 128 features = 4096 values, 16 per thread
    for (int idx = t; idx < NPB * HHALF; idx += 256) {
        int j = idx & (HHALF - 1);
        int node = idx >> 7;
        float v = b1[j]
                + feats[node][0] * w1[j]
                + feats[node][1] * w1[HHALF + j]
                + feats[node][2] * w1[2 * HHALF + j];
        hid[j][node] = fmaxf(v, 0.0f);
    }
    __syncthreads();

    // output layer: thread t owns output column c = t for all 32 nodes
    int c = t;
    float acc[NPB];
    float bc = b2[c];
#pragma unroll
    for (int p = 0; p < NPB; p++) acc[p] = bc;

    for (int j = 0; j < HHALF; j++) {
        float wj = w2[j * HID + c];
        const float4* hv = (const float4*)&hid[j][0];
#pragma unroll
        for (int q = 0; q < NPB / 4; q++) {
            float4 h4 = hv[q];
            acc[4 * q + 0] = fmaf(h4.x, wj, acc[4 * q + 0]);
            acc[4 * q + 1] = fmaf(h4.y, wj, acc[4 * q + 1]);
            acc[4 * q + 2] = fmaf(h4.z, wj, acc[4 * q + 2]);
            acc[4 * q + 3] = fmaf(h4.w, wj, acc[4 * q + 3]);
        }
    }
#pragma unroll
    for (int p = 0; p < NPB; p++) out[(n0 + p) * HID + c] = acc[p];
}

// ---------------- launch ----------------------------------------------------
extern "C" void kernel_launch(void* const* d_in, const int* in_sizes, int n_in,
                              void* d_out, int out_size) {
    const float*  x      = (const float*)d_in[0];
    const int*    ei     = (const int*)d_in[1];
    const float2* coords = (const float2*)d_in[2];
    const float*  w1     = (const float*)d_in[3];
    const float*  b1     = (const float*)d_in[4];
    const float*  w2     = (const float*)d_in[5];
    const float*  b2     = (const float*)d_in[6];
    float*        out    = (float*)d_out;

    const int* row = ei;
    const int* col = ei + N_EDGES;

    k_zero<<<(N_NODES + 255) / 256, 256>>>();
    k_degree<<<N_EDGES / 256, 256>>>(row);
    k_scan<<<1, 1024>>>();
    k_fill<<<N_EDGES / 256, 256>>>(row, col);
    k_density<<<dim3(N_NODES / 256, 8), 256>>>(coords);
    k_fvar<<<N_NODES, 256>>>(x);
    k_max<<<1, 1024>>>();
    k_mlp<<<N_NODES / NPB, 256>>>(w1, b1, w2, b2, out);
}

// round 3
// speedup vs baseline: 1.5471x; 1.5471x over previous
#include <cuda_runtime.h>

#define N_NODES 16384
#define N_EDGES 524288
#define HID 256
#define HHALF 128
#define R2 2500.0f
#define EPSV 1e-8f
#define NPB 32      // nodes per block in MLP kernel
#define GRIDC 20    // spatial grid cells per axis (cell = 50.0 = RADIUS)
#define NCELLS (GRIDC * GRIDC)

// ---------------- scratch (device globals: no allocation allowed) ----------
__device__ int    g_deg[N_NODES];
__device__ int    g_fill[N_NODES];
__device__ int    g_csr_ptr[N_NODES + 1];
__device__ int    g_csr_col[N_EDGES];
__device__ float  g_density[N_NODES];   // raw in-radius count (incl. self)
__device__ float  g_fvar[N_NODES];
__device__ float  g_max[4];             // [0]=max deg, [1]=max density, [2]=max fvar
// spatial binning scratch
__device__ int    g_cell_cnt[NCELLS];
__device__ int    g_cell_fill[NCELLS];
__device__ int    g_cell_ptr[NCELLS + 1];
__device__ float2 g_sorted_xy[N_NODES];
__device__ int    g_sorted_id[N_NODES];

__device__ __forceinline__ int cell_of(float v) {
    int c = (int)(v * 0.02f);           // v / 50
    return min(max(c, 0), GRIDC - 1);
}

// ---------------- init -----------------------------------------------------
__global__ void k_zero() {
    int i = blockIdx.x * blockDim.x + threadIdx.x;
    if (i < N_NODES) { g_deg[i] = 0; g_fill[i] = 0; }
    if (i < NCELLS) { g_cell_cnt[i] = 0; g_cell_fill[i] = 0; }
    if (i < 4) g_max[i] = 0.0f;
}

// ---------------- spatial binning ------------------------------------------
__global__ void k_bin_count(const float2* __restrict__ coords) {
    int i = blockIdx.x * blockDim.x + threadIdx.x;
    if (i < N_NODES) {
        float2 p = coords[i];
        atomicAdd(&g_cell_cnt[cell_of(p.y) * GRIDC + cell_of(p.x)], 1);
    }
}

__global__ void k_bin_scan() {
    __shared__ int s[512];
    int t = threadIdx.x;
    int v = (t < NCELLS) ? g_cell_cnt[t] : 0;
    s[t] = v;
    __syncthreads();
    for (int off = 1; off < 512; off <<= 1) {
        int u = (t >= off) ? s[t - off] : 0;
        __syncthreads();
        s[t] += u;
        __syncthreads();
    }
    if (t < NCELLS) g_cell_ptr[t] = s[t] - v;       // exclusive
    if (t == NCELLS - 1) g_cell_ptr[NCELLS] = s[t];
}

__global__ void k_bin_fill(const float2* __restrict__ coords) {
    int i = blockIdx.x * blockDim.x + threadIdx.x;
    if (i < N_NODES) {
        float2 p = coords[i];
        int c = cell_of(p.y) * GRIDC + cell_of(p.x);
        int pos = g_cell_ptr[c] + atomicAdd(&g_cell_fill[c], 1);
        g_sorted_xy[pos] = p;
        g_sorted_id[pos] = i;
    }
}

// ---------------- spatial density (binned) ---------------------------------
__global__ void k_density_b() {
    int i = blockIdx.x * blockDim.x + threadIdx.x;
    if (i >= N_NODES) return;
    float2 p = g_sorted_xy[i];
    int cx = cell_of(p.x), cy = cell_of(p.y);
    int y0 = max(cy - 1, 0), y1 = min(cy + 1, GRIDC - 1);
    int x0 = max(cx - 1, 0), x1 = min(cx + 1, GRIDC - 1);
    int cnt = 0;
    for (int yy = y0; yy <= y1; yy++) {
        int b = g_cell_ptr[yy * GRIDC + x0];
        int e = g_cell_ptr[yy * GRIDC + x1 + 1];   // cells contiguous in x
        for (int k = b; k < e; k++) {
            float2 q = g_sorted_xy[k];
            float dx = p.x - q.x;
            float dy = p.y - q.y;
            cnt += (fmaf(dx, dx, dy * dy) <= R2) ? 1 : 0;
        }
    }
    g_density[g_sorted_id[i]] = (float)cnt;
}

// ---------------- degree ---------------------------------------------------
__global__ void k_degree(const int* __restrict__ row) {
    int e = blockIdx.x * blockDim.x + threadIdx.x;
    if (e < N_EDGES) atomicAdd(&g_deg[row[e]], 1);
}

// ---------------- exclusive scan of degrees (single block, 1024 thr) -------
__global__ void k_scan() {
    __shared__ int s[1024];
    int t = threadIdx.x;
    int base = t * 16;
    int loc[16];
    int sum = 0;
#pragma unroll
    for (int k = 0; k < 16; k++) { loc[k] = sum; sum += g_deg[base + k]; }
    s[t] = sum;
    __syncthreads();
    for (int off = 1; off < 1024; off <<= 1) {
        int v = (t >= off) ? s[t - off] : 0;
        __syncthreads();
        s[t] += v;
        __syncthreads();
    }
    int excl = (t == 0) ? 0 : s[t - 1];
#pragma unroll
    for (int k = 0; k < 16; k++) g_csr_ptr[base + k] = excl + loc[k];
    if (t == 1023) g_csr_ptr[N_NODES] = s[1023];
}

// ---------------- CSR fill -------------------------------------------------
__global__ void k_fill(const int* __restrict__ row, const int* __restrict__ col) {
    int e = blockIdx.x * blockDim.x + threadIdx.x;
    if (e < N_EDGES) {
        int r = row[e];
        int pos = g_csr_ptr[r] + atomicAdd(&g_fill[r], 1);
        g_csr_col[pos] = col[e];
    }
}

// ---------------- local feature variance (block of 64 per node, float4) ----
__global__ void k_fvar(const float4* __restrict__ x4) {
    int n = blockIdx.x;
    int t = threadIdx.x;            // 64 threads: one float4 per thread
    int beg = g_csr_ptr[n], end = g_csr_ptr[n + 1];

    float4 s0 = {0, 0, 0, 0}, s1 = {0, 0, 0, 0}, s2 = {0, 0, 0, 0}, s3 = {0, 0, 0, 0};
    int e = beg;
    for (; e + 4 <= end; e += 4) {
        int c0 = g_csr_col[e];
        int c1 = g_csr_col[e + 1];
        int c2 = g_csr_col[e + 2];
        int c3 = g_csr_col[e + 3];
        float4 v0 = x4[c0 * 64 + t];
        float4 v1 = x4[c1 * 64 + t];
        float4 v2 = x4[c2 * 64 + t];
        float4 v3 = x4[c3 * 64 + t];
        s0.x += v0.x; s0.y += v0.y; s0.z += v0.z; s0.w += v0.w;
        s1.x += v1.x; s1.y += v1.y; s1.z += v1.z; s1.w += v1.w;
        s2.x += v2.x; s2.y += v2.y; s2.z += v2.z; s2.w += v2.w;
        s3.x += v3.x; s3.y += v3.y; s3.z += v3.z; s3.w += v3.w;
    }
    for (; e < end; e++) {
        float4 v = x4[g_csr_col[e] * 64 + t];
        s0.x += v.x; s0.y += v.y; s0.z += v.z; s0.w += v.w;
    }
    float sx = (s0.x + s1.x) + (s2.x + s3.x);
    float sy = (s0.y + s1.y) + (s2.y + s3.y);
    float sz = (s0.z + s1.z) + (s2.z + s3.z);
    float sw = (s0.w + s1.w) + (s2.w + s3.w);

    float inv = 1.0f / (float)((end - beg) > 1 ? (end - beg) : 1);
    float4 xv = x4[n * 64 + t];
    float dx = xv.x - sx * inv;
    float dy = xv.y - sy * inv;
    float dz = xv.z - sz * inv;
    float dw = xv.w - sw * inv;
    float local = fmaf(dx, dx, fmaf(dy, dy, fmaf(dz, dz, dw * dw)));

    // reduce over 64 threads (2 warps)
#pragma unroll
    for (int off = 16; off > 0; off >>= 1)
        local += __shfl_down_sync(0xFFFFFFFFu, local, off);
    __shared__ float warpsum[2];
    if ((t & 31) == 0) warpsum[t >> 5] = local;
    __syncthreads();
    if (t == 0) g_fvar[n] = sqrtf(warpsum[0] + warpsum[1]);
}

// ---------------- maxima reduction -----------------------------------------
__global__ void k_max() {
    __shared__ float m0[1024], m1[1024], m2[1024];
    int t = threadIdx.x;
    float a = 0.f, b = 0.f, c = 0.f;
    for (int i = t; i < N_NODES; i += 1024) {
        a = fmaxf(a, (float)g_deg[i]);
        b = fmaxf(b, g_density[i] - 1.0f);
        c = fmaxf(c, g_fvar[i]);
    }
    m0[t] = a; m1[t] = b; m2[t] = c;
    __syncthreads();
    for (int off = 512; off > 0; off >>= 1) {
        if (t < off) {
            m0[t] = fmaxf(m0[t], m0[t + off]);
            m1[t] = fmaxf(m1[t], m1[t + off]);
            m2[t] = fmaxf(m2[t], m2[t + off]);
        }
        __syncthreads();
    }
    if (t == 0) { g_max[0] = m0[0]; g_max[1] = m1[0]; g_max[2] = m2[0]; }
}

// ---------------- MLP: 32 nodes per block, 256 output cols -----------------
__global__ void k_mlp(const float* __restrict__ w1, const float* __restrict__ b1,
                      const float* __restrict__ w2, const float* __restrict__ b2,
                      float* __restrict__ out) {
    __shared__ float feats[NPB][3];
    __shared__ __align__(16) float hid[HHALF][NPB];   // transposed: [j][node]
    int t = threadIdx.x;
    int n0 = blockIdx.x * NPB;

    if (t < NPB) {
        int n = n0 + t;
        float invd   = 1.0f / (g_max[0] + EPSV);
        float invden = 1.0f / (g_max[1] + EPSV);
        float invf   = 1.0f / (g_max[2] + EPSV);
        feats[t][0] = (float)g_deg[n] * invd;
        feats[t][1] = (g_density[n] - 1.0f) * invden;
        feats[t][2] = g_fvar[n] * invf;
    }
    __syncthreads();

    for (int idx = t; idx < NPB * HHALF; idx += 256) {
        int j = idx & (HHALF - 1);
        int node = idx >> 7;
        float v = b1[j]
                + feats[node][0] * w1[j]
                + feats[node][1] * w1[HHALF + j]
                + feats[node][2] * w1[2 * HHALF + j];
        hid[j][node] = fmaxf(v, 0.0f);
    }
    __syncthreads();

    int c = t;
    float acc[NPB];
    float bc = b2[c];
#pragma unroll
    for (int p = 0; p < NPB; p++) acc[p] = bc;

    for (int j = 0; j < HHALF; j++) {
        float wj = w2[j * HID + c];
        const float4* hv = (const float4*)&hid[j][0];
#pragma unroll
        for (int q = 0; q < NPB / 4; q++) {
            float4 h4 = hv[q];
            acc[4 * q + 0] = fmaf(h4.x, wj, acc[4 * q + 0]);
            acc[4 * q + 1] = fmaf(h4.y, wj, acc[4 * q + 1]);
            acc[4 * q + 2] = fmaf(h4.z, wj, acc[4 * q + 2]);
            acc[4 * q + 3] = fmaf(h4.w, wj, acc[4 * q + 3]);
        }
    }
#pragma unroll
    for (int p = 0; p < NPB; p++) out[(n0 + p) * HID + c] = acc[p];
}

// ---------------- launch ----------------------------------------------------
extern "C" void kernel_launch(void* const* d_in, const int* in_sizes, int n_in,
                              void* d_out, int out_size) {
    const float*  x      = (const float*)d_in[0];
    const int*    ei     = (const int*)d_in[1];
    const float2* coords = (const float2*)d_in[2];
    const float*  w1     = (const float*)d_in[3];
    const float*  b1     = (const float*)d_in[4];
    const float*  w2     = (const float*)d_in[5];
    const float*  b2     = (const float*)d_in[6];
    float*        out    = (float*)d_out;

    const int* row = ei;
    const int* col = ei + N_EDGES;

    k_zero<<<(N_NODES + 255) / 256, 256>>>();
    k_bin_count<<<N_NODES / 256, 256>>>(coords);
    k_bin_scan<<<1, 512>>>();
    k_bin_fill<<<N_NODES / 256, 256>>>(coords);
    k_density_b<<<N_NODES / 256, 256>>>();
    k_degree<<<N_EDGES / 256, 256>>>(row);
    k_scan<<<1, 1024>>>();
    k_fill<<<N_EDGES / 256, 256>>>(row, col);
    k_fvar<<<N_NODES, 64>>>((const float4*)x);
    k_max<<<1, 1024>>>();
    k_mlp<<<N_NODES / NPB, 256>>>(w1, b1, w2, b2, out);
}

// round 4
// speedup vs baseline: 1.8286x; 1.1820x over previous
#include <cuda_runtime.h>

#define N_NODES 16384
#define N_EDGES 524288
#define HID 256
#define HHALF 128
#define R2 2500.0f
#define EPSV 1e-8f
#define NPB 32      // nodes per block in MLP kernel
#define GRIDC 20    // spatial grid cells per axis (cell = 50.0 = RADIUS)
#define NCELLS (GRIDC * GRIDC)

// ---------------- scratch (device globals: no allocation allowed) ----------
__device__ int    g_deg[N_NODES];
__device__ int    g_fill[N_NODES];
__device__ int    g_csr_ptr[N_NODES + 1];
__device__ int    g_csr_col[N_EDGES];
__device__ float  g_density[N_NODES];   // raw in-radius count (incl. self)
__device__ float  g_fvar[N_NODES];
__device__ float  g_max[4];             // [0]=max deg, [1]=max(density-1), [2]=max fvar
// spatial binning scratch
__device__ int    g_cell_cnt[NCELLS];
__device__ int    g_cell_fill[NCELLS];
__device__ int    g_cell_ptr[NCELLS + 1];
__device__ int    g_node_cell[N_NODES];
__device__ float2 g_sorted_xy[N_NODES];
__device__ int    g_sorted_id[N_NODES];

__device__ __forceinline__ int cell_of(float v) {
    int c = (int)(v * 0.02f);           // v / 50
    return min(max(c, 0), GRIDC - 1);
}

// ---------------- K1: init --------------------------------------------------
__global__ void k_zero() {
    int i = blockIdx.x * blockDim.x + threadIdx.x;
    if (i < N_NODES) { g_deg[i] = 0; g_fill[i] = 0; }
    if (i < NCELLS) { g_cell_cnt[i] = 0; g_cell_fill[i] = 0; }
    if (i < 4) g_max[i] = 0.0f;
}

// ---------------- K2: fused counts (bin histogram || degree) ---------------
// blocks [0,64): node binning; blocks [64, 64+2048): edge degree
__global__ void k_count(const float2* __restrict__ coords, const int* __restrict__ row) {
    int b = blockIdx.x, t = threadIdx.x;
    if (b < 64) {
        int i = b * 256 + t;
        float2 p = coords[i];
        int c = cell_of(p.y) * GRIDC + cell_of(p.x);
        g_node_cell[i] = c;
        atomicAdd(&g_cell_cnt[c], 1);
    } else {
        int e = (b - 64) * 256 + t;
        atomicAdd(&g_deg[row[e]], 1);
    }
}

// ---------------- K3: fused scans (block0: cells; block1: degrees + max) ---
__global__ void k_scans() {
    int t = threadIdx.x;
    if (blockIdx.x == 0) {
        // exclusive scan over 400 cell counts (1024-thread Hillis-Steele)
        __shared__ int s[1024];
        int v = (t < NCELLS) ? g_cell_cnt[t] : 0;
        s[t] = v;
        __syncthreads();
        for (int off = 1; off < 1024; off <<= 1) {
            int u = (t >= off) ? s[t - off] : 0;
            __syncthreads();
            s[t] += u;
            __syncthreads();
        }
        if (t < NCELLS) g_cell_ptr[t] = s[t] - v;
        if (t == NCELLS - 1) g_cell_ptr[NCELLS] = s[t];
    } else {
        // exclusive scan over 16384 degrees + degree max
        __shared__ int s[1024];
        __shared__ int mx[1024];
        int base = t * 16;
        int loc[16];
        int sum = 0, m = 0;
#pragma unroll
        for (int k = 0; k < 16; k++) {
            int d = g_deg[base + k];
            loc[k] = sum; sum += d; m = max(m, d);
        }
        s[t] = sum; mx[t] = m;
        __syncthreads();
        for (int off = 1; off < 1024; off <<= 1) {
            int v = (t >= off) ? s[t - off] : 0;
            __syncthreads();
            s[t] += v;
            __syncthreads();
        }
        int excl = (t == 0) ? 0 : s[t - 1];
#pragma unroll
        for (int k = 0; k < 16; k++) g_csr_ptr[base + k] = excl + loc[k];
        if (t == 1023) g_csr_ptr[N_NODES] = s[1023];
        // max reduction
        for (int off = 512; off > 0; off >>= 1) {
            if (t < off) mx[t] = max(mx[t], mx[t + off]);
            __syncthreads();
        }
        if (t == 0) g_max[0] = (float)mx[0];
    }
}

// ---------------- K4: fused fills (bin fill || CSR fill, 4 edges/thread) ---
// blocks [0,64): bin fill; blocks [64, 64+512): CSR fill
__global__ void k_fills(const float2* __restrict__ coords,
                        const int* __restrict__ row, const int* __restrict__ col) {
    int b = blockIdx.x, t = threadIdx.x;
    if (b < 64) {
        int i = b * 256 + t;
        int c = g_node_cell[i];
        int pos = g_cell_ptr[c] + atomicAdd(&g_cell_fill[c], 1);
        g_sorted_xy[pos] = coords[i];
        g_sorted_id[pos] = i;
    } else {
        int idx = (b - 64) * 256 + t;          // idx in [0, 131072)
        int4 r4 = ((const int4*)row)[idx];
        int4 c4 = ((const int4*)col)[idx];
        int p0 = g_csr_ptr[r4.x] + atomicAdd(&g_fill[r4.x], 1);
        int p1 = g_csr_ptr[r4.y] + atomicAdd(&g_fill[r4.y], 1);
        int p2 = g_csr_ptr[r4.z] + atomicAdd(&g_fill[r4.z], 1);
        int p3 = g_csr_ptr[r4.w] + atomicAdd(&g_fill[r4.w], 1);
        g_csr_col[p0] = c4.x;
        g_csr_col[p1] = c4.y;
        g_csr_col[p2] = c4.z;
        g_csr_col[p3] = c4.w;
    }
}

// ---------------- K5: fused density || fvar, with inline maxima ------------
// blocks [0,64): density (1 node/thread); blocks [64, 64+4096): fvar (4 nodes/block)
__global__ void k_den_fvar(const float4* __restrict__ x4) {
    int b = blockIdx.x, t = threadIdx.x;
    if (b < 64) {
        // -------- density over sorted nodes --------
        int i = b * 256 + t;
        float2 p = g_sorted_xy[i];
        int cx = cell_of(p.x), cy = cell_of(p.y);
        int y0 = max(cy - 1, 0), y1 = min(cy + 1, GRIDC - 1);
        int x0 = max(cx - 1, 0), x1 = min(cx + 1, GRIDC - 1);
        int cnt = 0;
        for (int yy = y0; yy <= y1; yy++) {
            int bb = g_cell_ptr[yy * GRIDC + x0];
            int ee = g_cell_ptr[yy * GRIDC + x1 + 1];   // cells contiguous in x
            for (int k = bb; k < ee; k++) {
                float2 q = g_sorted_xy[k];
                float dx = p.x - q.x;
                float dy = p.y - q.y;
                cnt += (fmaf(dx, dx, dy * dy) <= R2) ? 1 : 0;
            }
        }
        g_density[g_sorted_id[i]] = (float)cnt;
        // block max of (cnt - 1)
        float v = (float)(cnt - 1);
#pragma unroll
        for (int off = 16; off > 0; off >>= 1)
            v = fmaxf(v, __shfl_down_sync(0xFFFFFFFFu, v, off));
        __shared__ float wm[8];
        if ((t & 31) == 0) wm[t >> 5] = v;
        __syncthreads();
        if (t == 0) {
            float m = wm[0];
#pragma unroll
            for (int w = 1; w < 8; w++) m = fmaxf(m, wm[w]);
            atomicMax((int*)&g_max[1], __float_as_int(m));
        }
    } else {
        // -------- fvar: 4 nodes per block, 64 threads per node --------
        int grp = t >> 6;            // 0..3
        int lane = t & 63;           // feature quad
        int n = (b - 64) * 4 + grp;
        int beg = g_csr_ptr[n], end = g_csr_ptr[n + 1];

        float4 s0 = {0,0,0,0}, s1 = {0,0,0,0}, s2 = {0,0,0,0}, s3 = {0,0,0,0};
        int e = beg;
        for (; e + 4 <= end; e += 4) {
            int c0 = g_csr_col[e];
            int c1 = g_csr_col[e + 1];
            int c2 = g_csr_col[e + 2];
            int c3 = g_csr_col[e + 3];
            float4 v0 = x4[c0 * 64 + lane];
            float4 v1 = x4[c1 * 64 + lane];
            float4 v2 = x4[c2 * 64 + lane];
            float4 v3 = x4[c3 * 64 + lane];
            s0.x += v0.x; s0.y += v0.y; s0.z += v0.z; s0.w += v0.w;
            s1.x += v1.x; s1.y += v1.y; s1.z += v1.z; s1.w += v1.w;
            s2.x += v2.x; s2.y += v2.y; s2.z += v2.z; s2.w += v2.w;
            s3.x += v3.x; s3.y += v3.y; s3.z += v3.z; s3.w += v3.w;
        }
        for (; e < end; e++) {
            float4 v = x4[g_csr_col[e] * 64 + lane];
            s0.x += v.x; s0.y += v.y; s0.z += v.z; s0.w += v.w;
        }
        float sx = (s0.x + s1.x) + (s2.x + s3.x);
        float sy = (s0.y + s1.y) + (s2.y + s3.y);
        float sz = (s0.z + s1.z) + (s2.z + s3.z);
        float sw = (s0.w + s1.w) + (s2.w + s3.w);

        float inv = 1.0f / (float)((end - beg) > 1 ? (end - beg) : 1);
        float4 xv = x4[n * 64 + lane];
        float dx = xv.x - sx * inv;
        float dy = xv.y - sy * inv;
        float dz = xv.z - sz * inv;
        float dw = xv.w - sw * inv;
        float local = fmaf(dx, dx, fmaf(dy, dy, fmaf(dz, dz, dw * dw)));

        // within-warp reduce (32 lanes), then combine warp pairs
#pragma unroll
        for (int off = 16; off > 0; off >>= 1)
            local += __shfl_down_sync(0xFFFFFFFFu, local, off);
        __shared__ float ws[8];
        __shared__ float fv4[4];
        if ((t & 31) == 0) ws[t >> 5] = local;
        __syncthreads();
        if (lane == 0) {
            float fv = sqrtf(ws[2 * grp] + ws[2 * grp + 1]);
            g_fvar[n] = fv;
            fv4[grp] = fv;
        }
        __syncthreads();
        if (t == 0) {
            float m = fmaxf(fmaxf(fv4[0], fv4[1]), fmaxf(fv4[2], fv4[3]));
            atomicMax((int*)&g_max[2], __float_as_int(m));
        }
    }
}

// ---------------- K6: MLP: 32 nodes per block, 256 output cols -------------
__global__ void k_mlp(const float* __restrict__ w1, const float* __restrict__ b1,
                      const float* __restrict__ w2, const float* __restrict__ b2,
                      float* __restrict__ out) {
    __shared__ float feats[NPB][3];
    __shared__ __align__(16) float hid[HHALF][NPB];   // transposed: [j][node]
    int t = threadIdx.x;
    int n0 = blockIdx.x * NPB;

    if (t < NPB) {
        int n = n0 + t;
        float invd   = 1.0f / (g_max[0] + EPSV);
        float invden = 1.0f / (g_max[1] + EPSV);
        float invf   = 1.0f / (g_max[2] + EPSV);
        feats[t][0] = (float)g_deg[n] * invd;
        feats[t][1] = (g_density[n] - 1.0f) * invden;
        feats[t][2] = g_fvar[n] * invf;
    }
    __syncthreads();

    for (int idx = t; idx < NPB * HHALF; idx += 256) {
        int j = idx & (HHALF - 1);
        int node = idx >> 7;
        float v = b1[j]
                + feats[node][0] * w1[j]
                + feats[node][1] * w1[HHALF + j]
                + feats[node][2] * w1[2 * HHALF + j];
        hid[j][node] = fmaxf(v, 0.0f);
    }
    __syncthreads();

    int c = t;
    float acc[NPB];
    float bc = b2[c];
#pragma unroll
    for (int p = 0; p < NPB; p++) acc[p] = bc;

    for (int j = 0; j < HHALF; j++) {
        float wj = w2[j * HID + c];
        const float4* hv = (const float4*)&hid[j][0];
#pragma unroll
        for (int q = 0; q < NPB / 4; q++) {
            float4 h4 = hv[q];
            acc[4 * q + 0] = fmaf(h4.x, wj, acc[4 * q + 0]);
            acc[4 * q + 1] = fmaf(h4.y, wj, acc[4 * q + 1]);
            acc[4 * q + 2] = fmaf(h4.z, wj, acc[4 * q + 2]);
            acc[4 * q + 3] = fmaf(h4.w, wj, acc[4 * q + 3]);
        }
    }
#pragma unroll
    for (int p = 0; p < NPB; p++) out[(n0 + p) * HID + c] = acc[p];
}

// ---------------- launch ----------------------------------------------------
extern "C" void kernel_launch(void* const* d_in, const int* in_sizes, int n_in,
                              void* d_out, int out_size) {
    const float*  x      = (const float*)d_in[0];
    const int*    ei     = (const int*)d_in[1];
    const float2* coords = (const float2*)d_in[2];
    const float*  w1     = (const float*)d_in[3];
    const float*  b1     = (const float*)d_in[4];
    const float*  w2     = (const float*)d_in[5];
    const float*  b2     = (const float*)d_in[6];
    float*        out    = (float*)d_out;

    const int* row = ei;
    const int* col = ei + N_EDGES;

    k_zero   <<<64, 256>>>();
    k_count  <<<64 + N_EDGES / 256, 256>>>(coords, row);
    k_scans  <<<2, 1024>>>();
    k_fills  <<<64 + N_EDGES / 1024, 256>>>(coords, row, col);
    k_den_fvar<<<64 + N_NODES / 4, 256>>>((const float4*)x);
    k_mlp    <<<N_NODES / NPB, 256>>>(w1, b1, w2, b2, out);
}

// round 6
// speedup vs baseline: 1.9704x; 1.0775x over previous
#include <cuda_runtime.h>
#include <cuda_bf16.h>

#define N_NODES 16384
#define N_EDGES 524288
#define HID 256
#define HHALF 128
#define R2 2500.0f
#define EPSV 1e-8f
#define NPB 32      // nodes per block in MLP kernel
#define GRIDC 20    // spatial grid cells per axis (cell = 50.0 = RADIUS)
#define NCELLS (GRIDC * GRIDC)

// ---------------- scratch (device globals: no allocation allowed) ----------
__device__ int    g_deg[N_NODES];
__device__ int    g_fill[N_NODES];
__device__ int    g_csr_ptr[N_NODES + 1];
__device__ int    g_csr_col[N_EDGES];
__device__ float  g_density[N_NODES];
__device__ float  g_fvar[N_NODES];
__device__ float  g_max[4];             // [0]=max deg, [1]=max(density-1), [2]=max fvar
__device__ unsigned int g_xh[N_NODES * HHALF];   // x in packed bf16x2, 8 MB
// spatial binning scratch
__device__ int    g_cell_cnt[NCELLS];
__device__ int    g_cell_fill[NCELLS];
__device__ int    g_cell_ptr[NCELLS + 1];
__device__ int    g_node_cell[N_NODES];
__device__ float2 g_sorted_xy[N_NODES];
__device__ int    g_sorted_id[N_NODES];

__device__ __forceinline__ int cell_of(float v) {
    int c = (int)(v * 0.02f);           // v / 50
    return min(max(c, 0), GRIDC - 1);
}

// pack two floats into one bf16x2 word: low 16 bits = first value
__device__ __forceinline__ unsigned int pack_bf(float lo, float hi) {
    unsigned int l = (unsigned int)__bfloat16_as_ushort(__float2bfloat16(lo));
    unsigned int h = (unsigned int)__bfloat16_as_ushort(__float2bfloat16(hi));
    return l | (h << 16);
}

// unpack bf16x2 word and accumulate into two f32 sums (2 ALU ops + 2 FADD)
__device__ __forceinline__ void bfacc(unsigned int u, float& a, float& b) {
    a += __uint_as_float(u << 16);
    b += __uint_as_float(u & 0xFFFF0000u);
}

// ---------------- K1: init --------------------------------------------------
__global__ void k_zero() {
    int i = blockIdx.x * blockDim.x + threadIdx.x;
    if (i < N_NODES) { g_deg[i] = 0; g_fill[i] = 0; }
    if (i < NCELLS) { g_cell_cnt[i] = 0; g_cell_fill[i] = 0; }
    if (i < 4) g_max[i] = 0.0f;
}

// ---------------- K2: fused counts (bin hist || degree || bf16 convert) ----
// blocks [0,64): node binning; [64, 2112): edge degree; [2112, 4160): convert
__global__ void k_count(const float2* __restrict__ coords, const int* __restrict__ row,
                        const float4* __restrict__ x4) {
    int b = blockIdx.x, t = threadIdx.x;
    if (b < 64) {
        int i = b * 256 + t;
        float2 p = coords[i];
        int c = cell_of(p.y) * GRIDC + cell_of(p.x);
        g_node_cell[i] = c;
        atomicAdd(&g_cell_cnt[c], 1);
    } else if (b < 64 + 2048) {
        int e = (b - 64) * 256 + t;
        atomicAdd(&g_deg[row[e]], 1);
    } else {
        // convert 8 floats -> 4 bf16x2 words per thread
        int idx = (b - 2112) * 256 + t;            // [0, 524288)
        float4 a = x4[2 * idx];
        float4 c = x4[2 * idx + 1];
        uint4 o;
        o.x = pack_bf(a.x, a.y);
        o.y = pack_bf(a.z, a.w);
        o.z = pack_bf(c.x, c.y);
        o.w = pack_bf(c.z, c.w);
        ((uint4*)g_xh)[idx] = o;
    }
}

// ---------------- K3: fused scans (shuffle-based) ---------------------------
__global__ void k_scans() {
    int t = threadIdx.x;
    int lane = t & 31, warp = t >> 5;
    if (blockIdx.x == 0) {
        // exclusive scan over 400 cell counts
        int v = (t < NCELLS) ? g_cell_cnt[t] : 0;
        int s = v;
#pragma unroll
        for (int o = 1; o < 32; o <<= 1) {
            int u = __shfl_up_sync(0xFFFFFFFFu, s, o);
            if (lane >= o) s += u;
        }
        __shared__ int wt[32];
        if (lane == 31) wt[warp] = s;
        __syncthreads();
        if (warp == 0) {
            int w = wt[lane];
#pragma unroll
            for (int o = 1; o < 32; o <<= 1) {
                int u = __shfl_up_sync(0xFFFFFFFFu, w, o);
                if (lane >= o) w += u;
            }
            wt[lane] = w;
        }
        __syncthreads();
        int incl = s + (warp > 0 ? wt[warp - 1] : 0);
        if (t < NCELLS) g_cell_ptr[t] = incl - v;
        if (t == NCELLS - 1) g_cell_ptr[NCELLS] = incl;
    } else {
        // exclusive scan over 16384 degrees + degree max
        int base = t * 16;
        int loc[16];
        int sum = 0, m = 0;
#pragma unroll
        for (int k = 0; k < 16; k++) {
            int d = g_deg[base + k];
            loc[k] = sum; sum += d; m = max(m, d);
        }
        int s = sum;
#pragma unroll
        for (int o = 1; o < 32; o <<= 1) {
            int u = __shfl_up_sync(0xFFFFFFFFu, s, o);
            if (lane >= o) s += u;
        }
#pragma unroll
        for (int o = 16; o > 0; o >>= 1)
            m = max(m, __shfl_down_sync(0xFFFFFFFFu, m, o));
        __shared__ int wt[32];
        __shared__ int wm[32];
        if (lane == 31) wt[warp] = s;
        if (lane == 0) wm[warp] = m;
        __syncthreads();
        if (warp == 0) {
            int w = wt[lane];
#pragma unroll
            for (int o = 1; o < 32; o <<= 1) {
                int u = __shfl_up_sync(0xFFFFFFFFu, w, o);
                if (lane >= o) w += u;
            }
            wt[lane] = w;
            int mm = wm[lane];
#pragma unroll
            for (int o = 16; o > 0; o >>= 1)
                mm = max(mm, __shfl_down_sync(0xFFFFFFFFu, mm, o));
            if (lane == 0) g_max[0] = (float)mm;
        }
        __syncthreads();
        int excl = s - sum + (warp > 0 ? wt[warp - 1] : 0);
#pragma unroll
        for (int k = 0; k < 16; k++) g_csr_ptr[base + k] = excl + loc[k];
        if (t == 1023) g_csr_ptr[N_NODES] = excl + sum;
    }
}

// ---------------- K4: fused fills (bin fill || CSR fill, 8 edges/thread) ---
// blocks [0,64): bin fill; blocks [64, 64+256): CSR fill
__global__ void k_fills(const float2* __restrict__ coords,
                        const int* __restrict__ row, const int* __restrict__ col) {
    int b = blockIdx.x, t = threadIdx.x;
    if (b < 64) {
        int i = b * 256 + t;
        int c = g_node_cell[i];
        int pos = g_cell_ptr[c] + atomicAdd(&g_cell_fill[c], 1);
        g_sorted_xy[pos] = coords[i];
        g_sorted_id[pos] = i;
    } else {
        int idx = (b - 64) * 256 + t;          // idx in [0, 65536)
        const int4* rows4 = (const int4*)row;
        const int4* cols4 = (const int4*)col;
#pragma unroll
        for (int h = 0; h < 2; h++) {
            int4 r4 = rows4[2 * idx + h];
            int4 c4 = cols4[2 * idx + h];
            int p0 = g_csr_ptr[r4.x] + atomicAdd(&g_fill[r4.x], 1);
            int p1 = g_csr_ptr[r4.y] + atomicAdd(&g_fill[r4.y], 1);
            int p2 = g_csr_ptr[r4.z] + atomicAdd(&g_fill[r4.z], 1);
            int p3 = g_csr_ptr[r4.w] + atomicAdd(&g_fill[r4.w], 1);
            g_csr_col[p0] = c4.x;
            g_csr_col[p1] = c4.y;
            g_csr_col[p2] = c4.z;
            g_csr_col[p3] = c4.w;
        }
    }
}

// ---------------- K5: fused density || fvar (bf16 gather) ------------------
// blocks [0,64): density (1 node/thread); blocks [64, 64+2048): fvar (1 warp/node)
__global__ void k_den_fvar(const float4* __restrict__ x4) {
    int b = blockIdx.x, t = threadIdx.x;
    if (b < 64) {
        int i = b * 256 + t;
        float2 p = g_sorted_xy[i];
        int cx = cell_of(p.x), cy = cell_of(p.y);
        int y0 = max(cy - 1, 0), y1 = min(cy + 1, GRIDC - 1);
        int x0 = max(cx - 1, 0), x1 = min(cx + 1, GRIDC - 1);
        int cnt = 0;
        for (int yy = y0; yy <= y1; yy++) {
            int bb = g_cell_ptr[yy * GRIDC + x0];
            int ee = g_cell_ptr[yy * GRIDC + x1 + 1];
            for (int k = bb; k < ee; k++) {
                float2 q = g_sorted_xy[k];
                float dx = p.x - q.x;
                float dy = p.y - q.y;
                cnt += (fmaf(dx, dx, dy * dy) <= R2) ? 1 : 0;
            }
        }
        g_density[g_sorted_id[i]] = (float)cnt;
        float v = (float)(cnt - 1);
#pragma unroll
        for (int off = 16; off > 0; off >>= 1)
            v = fmaxf(v, __shfl_down_sync(0xFFFFFFFFu, v, off));
        __shared__ float wm[8];
        if ((t & 31) == 0) wm[t >> 5] = v;
        __syncthreads();
        if (t == 0) {
            float m = wm[0];
#pragma unroll
            for (int w = 1; w < 8; w++) m = fmaxf(m, wm[w]);
            atomicMax((int*)&g_max[1], __float_as_int(m));
        }
    } else {
        // -------- fvar: 1 warp per node, lane owns 8 features ----------
        int warp = t >> 5, lane = t & 31;
        int n = (b - 64) * 8 + warp;
        int beg = g_csr_ptr[n], end = g_csr_ptr[n + 1];
        const uint4* xh = (const uint4*)g_xh;   // [N_NODES * 32]

        float s0 = 0, s1 = 0, s2 = 0, s3 = 0, s4 = 0, s5 = 0, s6 = 0, s7 = 0;
        int e = beg;
        for (; e + 4 <= end; e += 4) {
            int c0 = g_csr_col[e];
            int c1 = g_csr_col[e + 1];
            int c2 = g_csr_col[e + 2];
            int c3 = g_csr_col[e + 3];
            uint4 v0 = xh[c0 * 32 + lane];
            uint4 v1 = xh[c1 * 32 + lane];
            uint4 v2 = xh[c2 * 32 + lane];
            uint4 v3 = xh[c3 * 32 + lane];
            bfacc(v0.x, s0, s1); bfacc(v0.y, s2, s3); bfacc(v0.z, s4, s5); bfacc(v0.w, s6, s7);
            bfacc(v1.x, s0, s1); bfacc(v1.y, s2, s3); bfacc(v1.z, s4, s5); bfacc(v1.w, s6, s7);
            bfacc(v2.x, s0, s1); bfacc(v2.y, s2, s3); bfacc(v2.z, s4, s5); bfacc(v2.w, s6, s7);
            bfacc(v3.x, s0, s1); bfacc(v3.y, s2, s3); bfacc(v3.z, s4, s5); bfacc(v3.w, s6, s7);
        }
        for (; e < end; e++) {
            uint4 v = xh[g_csr_col[e] * 32 + lane];
            bfacc(v.x, s0, s1); bfacc(v.y, s2, s3); bfacc(v.z, s4, s5); bfacc(v.w, s6, s7);
        }

        float inv = 1.0f / (float)((end - beg) > 1 ? (end - beg) : 1);
        float4 xa = x4[n * 64 + lane * 2];
        float4 xb = x4[n * 64 + lane * 2 + 1];
        float d0 = xa.x - s0 * inv;
        float d1 = xa.y - s1 * inv;
        float d2 = xa.z - s2 * inv;
        float d3 = xa.w - s3 * inv;
        float d4 = xb.x - s4 * inv;
        float d5 = xb.y - s5 * inv;
        float d6 = xb.z - s6 * inv;
        float d7 = xb.w - s7 * inv;
        float local = fmaf(d0, d0, fmaf(d1, d1, fmaf(d2, d2, d3 * d3)))
                    + fmaf(d4, d4, fmaf(d5, d5, fmaf(d6, d6, d7 * d7)));
#pragma unroll
        for (int off = 16; off > 0; off >>= 1)
            local += __shfl_down_sync(0xFFFFFFFFu, local, off);

        __shared__ float fv8[8];
        if (lane == 0) {
            float fv = sqrtf(local);
            g_fvar[n] = fv;
            fv8[warp] = fv;
        }
        __syncthreads();
        if (t == 0) {
            float m = fv8[0];
#pragma unroll
            for (int w = 1; w < 8; w++) m = fmaxf(m, fv8[w]);
            atomicMax((int*)&g_max[2], __float_as_int(m));
        }
    }
}

// ---------------- K6: MLP: 32 nodes per block, 256 output cols -------------
__global__ void k_mlp(const float* __restrict__ w1, const float* __restrict__ b1,
                      const float* __restrict__ w2, const float* __restrict__ b2,
                      float* __restrict__ out) {
    __shared__ float feats[NPB][3];
    __shared__ __align__(16) float hid[HHALF][NPB];   // transposed: [j][node]
    int t = threadIdx.x;
    int n0 = blockIdx.x * NPB;

    if (t < NPB) {
        int n = n0 + t;
        float invd   = 1.0f / (g_max[0] + EPSV);
        float invden = 1.0f / (g_max[1] + EPSV);
        float invf   = 1.0f / (g_max[2] + EPSV);
        feats[t][0] = (float)g_deg[n] * invd;
        feats[t][1] = (g_density[n] - 1.0f) * invden;
        feats[t][2] = g_fvar[n] * invf;
    }
    __syncthreads();

    for (int idx = t; idx < NPB * HHALF; idx += 256) {
        int j = idx & (HHALF - 1);
        int node = idx >> 7;
        float v = b1[j]
                + feats[node][0] * w1[j]
                + feats[node][1] * w1[HHALF + j]
                + feats[node][2] * w1[2 * HHALF + j];
        hid[j][node] = fmaxf(v, 0.0f);
    }
    __syncthreads();

    int c = t;
    float acc[NPB];
    float bc = b2[c];
#pragma unroll
    for (int p = 0; p < NPB; p++) acc[p] = bc;

    for (int j = 0; j < HHALF; j++) {
        float wj = w2[j * HID + c];
        const float4* hv = (const float4*)&hid[j][0];
#pragma unroll
        for (int q = 0; q < NPB / 4; q++) {
            float4 h4 = hv[q];
            acc[4 * q + 0] = fmaf(h4.x, wj, acc[4 * q + 0]);
            acc[4 * q + 1] = fmaf(h4.y, wj, acc[4 * q + 1]);
            acc[4 * q + 2] = fmaf(h4.z, wj, acc[4 * q + 2]);
            acc[4 * q + 3] = fmaf(h4.w, wj, acc[4 * q + 3]);
        }
    }
#pragma unroll
    for (int p = 0; p < NPB; p++) out[(n0 + p) * HID + c] = acc[p];
}

// ---------------- launch ----------------------------------------------------
extern "C" void kernel_launch(void* const* d_in, const int* in_sizes, int n_in,
                              void* d_out, int out_size) {
    const float*  x      = (const float*)d_in[0];
    const int*    ei     = (const int*)d_in[1];
    const float2* coords = (const float2*)d_in[2];
    const float*  w1     = (const float*)d_in[3];
    const float*  b1     = (const float*)d_in[4];
    const float*  w2     = (const float*)d_in[5];
    const float*  b2     = (const float*)d_in[6];
    float*        out    = (float*)d_out;

    const int* row = ei;
    const int* col = ei + N_EDGES;

    k_zero    <<<64, 256>>>();
    k_count   <<<64 + 2048 + 2048, 256>>>(coords, row, (const float4*)x);
    k_scans   <<<2, 1024>>>();
    k_fills   <<<64 + 256, 256>>>(coords, row, col);
    k_den_fvar<<<64 + 2048, 256>>>((const float4*)x);
    k_mlp     <<<N_NODES / NPB, 256>>>(w1, b1, w2, b2, out);
}

// round 8
// speedup vs baseline: 2.0887x; 1.0600x over previous
#include <cuda_runtime.h>
#include <cuda_bf16.h>

#define N_NODES 16384
#define N_EDGES 524288
#define HID 256
#define HHALF 128
#define R2 2500.0f
#define EPSV 1e-8f
#define NPB 32      // nodes per block in MLP kernel
#define GRIDC 20    // spatial grid cells per axis (cell = 50.0 = RADIUS)
#define NCELLS (GRIDC * GRIDC)

// ---------------- scratch (device globals: no allocation allowed) ----------
__device__ int    g_deg[N_NODES];
__device__ int    g_slot[N_EDGES];      // per-edge rank within its row
__device__ int    g_csr_ptr[N_NODES + 1];
__device__ int    g_csr_col[N_EDGES];
__device__ float  g_density[N_NODES];
__device__ float  g_fvar[N_NODES];
__device__ float  g_max[4];             // [0]=max deg, [1]=max(density-1), [2]=max fvar
__device__ unsigned int g_xh[N_NODES * HHALF];   // x in packed bf16x2, 8 MB
// spatial binning scratch
__device__ int    g_cell_cnt[NCELLS];
__device__ int    g_cell_fill[NCELLS];
__device__ int    g_cell_ptr[NCELLS + 1];
__device__ int    g_node_cell[N_NODES];
__device__ float2 g_sorted_xy[N_NODES];
__device__ int    g_sorted_id[N_NODES];

__device__ __forceinline__ int cell_of(float v) {
    int c = (int)(v * 0.02f);           // v / 50
    return min(max(c, 0), GRIDC - 1);
}

// pack two floats into one bf16x2 word: low 16 bits = first value
__device__ __forceinline__ unsigned int pack_bf(float lo, float hi) {
    unsigned int l = (unsigned int)__bfloat16_as_ushort(__float2bfloat16(lo));
    unsigned int h = (unsigned int)__bfloat16_as_ushort(__float2bfloat16(hi));
    return l | (h << 16);
}

// unpack bf16x2 word and accumulate into two f32 sums (2 ALU ops + 2 FADD)
__device__ __forceinline__ void bfacc(unsigned int u, float& a, float& b) {
    a += __uint_as_float(u << 16);
    b += __uint_as_float(u & 0xFFFF0000u);
}

// ---- packed f32x2 helpers (sm_103a: dual-lane FMA, full fp32 per lane) ----
__device__ __forceinline__ unsigned long long pk2(float a, float b) {
    unsigned long long r;
    asm("mov.b64 %0, {%1, %2};" : "=l"(r) : "f"(a), "f"(b));
    return r;
}
__device__ __forceinline__ void fma2(unsigned long long& d,
                                     unsigned long long a, unsigned long long b) {
    asm("fma.rn.f32x2 %0, %1, %2, %0;" : "+l"(d) : "l"(a), "l"(b));
}
__device__ __forceinline__ float2 upk(unsigned long long v) {
    float2 f;
    asm("mov.b64 {%0, %1}, %2;" : "=f"(f.x), "=f"(f.y) : "l"(v));
    return f;
}

// ---------------- K1: init --------------------------------------------------
__global__ void k_zero() {
    int i = blockIdx.x * blockDim.x + threadIdx.x;
    if (i < N_NODES) g_deg[i] = 0;
    if (i < NCELLS) { g_cell_cnt[i] = 0; g_cell_fill[i] = 0; }
    if (i < 4) g_max[i] = 0.0f;
}

// ---------------- K2: fused counts (bin hist || degree+slot || convert) ----
// blocks [0,64): node binning; [64, 2112): edge degree; [2112, 4160): convert
__global__ void k_count(const float2* __restrict__ coords, const int* __restrict__ row,
                        const float4* __restrict__ x4) {
    int b = blockIdx.x, t = threadIdx.x;
    if (b < 64) {
        int i = b * 256 + t;
        float2 p = coords[i];
        int c = cell_of(p.y) * GRIDC + cell_of(p.x);
        g_node_cell[i] = c;
        atomicAdd(&g_cell_cnt[c], 1);
    } else if (b < 64 + 2048) {
        int e = (b - 64) * 256 + t;
        g_slot[e] = atomicAdd(&g_deg[row[e]], 1);   // keep rank -> no atomics later
    } else {
        // convert 8 floats -> 4 bf16x2 words per thread
        int idx = (b - 2112) * 256 + t;            // [0, 524288)
        float4 a = x4[2 * idx];
        float4 c = x4[2 * idx + 1];
        uint4 o;
        o.x = pack_bf(a.x, a.y);
        o.y = pack_bf(a.z, a.w);
        o.z = pack_bf(c.x, c.y);
        o.w = pack_bf(c.z, c.w);
        ((uint4*)g_xh)[idx] = o;
    }
}

// ---------------- K3: fused scans (shuffle-based) ---------------------------
__global__ void k_scans() {
    int t = threadIdx.x;
    int lane = t & 31, warp = t >> 5;
    if (blockIdx.x == 0) {
        // exclusive scan over 400 cell counts
        int v = (t < NCELLS) ? g_cell_cnt[t] : 0;
        int s = v;
#pragma unroll
        for (int o = 1; o < 32; o <<= 1) {
            int u = __shfl_up_sync(0xFFFFFFFFu, s, o);
            if (lane >= o) s += u;
        }
        __shared__ int wt[32];
        if (lane == 31) wt[warp] = s;
        __syncthreads();
        if (warp == 0) {
            int w = wt[lane];
#pragma unroll
            for (int o = 1; o < 32; o <<= 1) {
                int u = __shfl_up_sync(0xFFFFFFFFu, w, o);
                if (lane >= o) w += u;
            }
            wt[lane] = w;
        }
        __syncthreads();
        int incl = s + (warp > 0 ? wt[warp - 1] : 0);
        if (t < NCELLS) g_cell_ptr[t] = incl - v;
        if (t == NCELLS - 1) g_cell_ptr[NCELLS] = incl;
    } else {
        // exclusive scan over 16384 degrees + degree max
        int base = t * 16;
        int loc[16];
        int sum = 0, m = 0;
#pragma unroll
        for (int k = 0; k < 16; k++) {
            int d = g_deg[base + k];
            loc[k] = sum; sum += d; m = max(m, d);
        }
        int s = sum;
#pragma unroll
        for (int o = 1; o < 32; o <<= 1) {
            int u = __shfl_up_sync(0xFFFFFFFFu, s, o);
            if (lane >= o) s += u;
        }
#pragma unroll
        for (int o = 16; o > 0; o >>= 1)
            m = max(m, __shfl_down_sync(0xFFFFFFFFu, m, o));
        __shared__ int wt[32];
        __shared__ int wm[32];
        if (lane == 31) wt[warp] = s;
        if (lane == 0) wm[warp] = m;
        __syncthreads();
        if (warp == 0) {
            int w = wt[lane];
#pragma unroll
            for (int o = 1; o < 32; o <<= 1) {
                int u = __shfl_up_sync(0xFFFFFFFFu, w, o);
                if (lane >= o) w += u;
            }
            wt[lane] = w;
            int mm = wm[lane];
#pragma unroll
            for (int o = 16; o > 0; o >>= 1)
                mm = max(mm, __shfl_down_sync(0xFFFFFFFFu, mm, o));
            if (lane == 0) g_max[0] = (float)mm;
        }
        __syncthreads();
        int excl = s - sum + (warp > 0 ? wt[warp - 1] : 0);
#pragma unroll
        for (int k = 0; k < 16; k++) g_csr_ptr[base + k] = excl + loc[k];
        if (t == 1023) g_csr_ptr[N_NODES] = excl + sum;
    }
}

// ---------------- K4: fused fills (bin fill || CSR fill — NO atomics) ------
// blocks [0,64): bin fill; blocks [64, 64+256): CSR fill, 8 edges/thread
__global__ void k_fills(const float2* __restrict__ coords,
                        const int* __restrict__ row, const int* __restrict__ col) {
    int b = blockIdx.x, t = threadIdx.x;
    if (b < 64) {
        int i = b * 256 + t;
        int c = g_node_cell[i];
        int pos = g_cell_ptr[c] + atomicAdd(&g_cell_fill[c], 1);
        g_sorted_xy[pos] = coords[i];
        g_sorted_id[pos] = i;
    } else {
        int idx = (b - 64) * 256 + t;          // idx in [0, 65536)
        const int4* rows4 = (const int4*)row;
        const int4* cols4 = (const int4*)col;
        const int4* slot4 = (const int4*)g_slot;
#pragma unroll
        for (int h = 0; h < 2; h++) {
            int4 r4 = rows4[2 * idx + h];
            int4 c4 = cols4[2 * idx + h];
            int4 s4 = slot4[2 * idx + h];
            g_csr_col[g_csr_ptr[r4.x] + s4.x] = c4.x;
            g_csr_col[g_csr_ptr[r4.y] + s4.y] = c4.y;
            g_csr_col[g_csr_ptr[r4.z] + s4.z] = c4.z;
            g_csr_col[g_csr_ptr[r4.w] + s4.w] = c4.w;
        }
    }
}

// ---------------- K5: fused density || fvar (bf16 gather) ------------------
// blocks [0,64): density (1 node/thread); blocks [64, 64+2048): fvar (1 warp/node)
__global__ void k_den_fvar(const float4* __restrict__ x4) {
    int b = blockIdx.x, t = threadIdx.x;
    if (b < 64) {
        int i = b * 256 + t;
        float2 p = g_sorted_xy[i];
        int cx = cell_of(p.x), cy = cell_of(p.y);
        int y0 = max(cy - 1, 0), y1 = min(cy + 1, GRIDC - 1);
        int x0 = max(cx - 1, 0), x1 = min(cx + 1, GRIDC - 1);
        int cnt = 0;
        for (int yy = y0; yy <= y1; yy++) {
            int bb = g_cell_ptr[yy * GRIDC + x0];
            int ee = g_cell_ptr[yy * GRIDC + x1 + 1];
            for (int k = bb; k < ee; k++) {
                float2 q = g_sorted_xy[k];
                float dx = p.x - q.x;
                float dy = p.y - q.y;
                cnt += (fmaf(dx, dx, dy * dy) <= R2) ? 1 : 0;
            }
        }
        g_density[g_sorted_id[i]] = (float)cnt;
        float v = (float)(cnt - 1);
#pragma unroll
        for (int off = 16; off > 0; off >>= 1)
            v = fmaxf(v, __shfl_down_sync(0xFFFFFFFFu, v, off));
        __shared__ float wm[8];
        if ((t & 31) == 0) wm[t >> 5] = v;
        __syncthreads();
        if (t == 0) {
            float m = wm[0];
#pragma unroll
            for (int w = 1; w < 8; w++) m = fmaxf(m, wm[w]);
            atomicMax((int*)&g_max[1], __float_as_int(m));
        }
    } else {
        // -------- fvar: 1 warp per node, lane owns 8 features ----------
        int warp = t >> 5, lane = t & 31;
        int n = (b - 64) * 8 + warp;
        int beg = g_csr_ptr[n], end = g_csr_ptr[n + 1];
        const uint4* xh = (const uint4*)g_xh;   // [N_NODES * 32]

        float s0 = 0, s1 = 0, s2 = 0, s3 = 0, s4 = 0, s5 = 0, s6 = 0, s7 = 0;
        int e = beg;
        for (; e + 4 <= end; e += 4) {
            int c0 = g_csr_col[e];
            int c1 = g_csr_col[e + 1];
            int c2 = g_csr_col[e + 2];
            int c3 = g_csr_col[e + 3];
            uint4 v0 = xh[c0 * 32 + lane];
            uint4 v1 = xh[c1 * 32 + lane];
            uint4 v2 = xh[c2 * 32 + lane];
            uint4 v3 = xh[c3 * 32 + lane];
            bfacc(v0.x, s0, s1); bfacc(v0.y, s2, s3); bfacc(v0.z, s4, s5); bfacc(v0.w, s6, s7);
            bfacc(v1.x, s0, s1); bfacc(v1.y, s2, s3); bfacc(v1.z, s4, s5); bfacc(v1.w, s6, s7);
            bfacc(v2.x, s0, s1); bfacc(v2.y, s2, s3); bfacc(v2.z, s4, s5); bfacc(v2.w, s6, s7);
            bfacc(v3.x, s0, s1); bfacc(v3.y, s2, s3); bfacc(v3.z, s4, s5); bfacc(v3.w, s6, s7);
        }
        for (; e < end; e++) {
            uint4 v = xh[g_csr_col[e] * 32 + lane];
            bfacc(v.x, s0, s1); bfacc(v.y, s2, s3); bfacc(v.z, s4, s5); bfacc(v.w, s6, s7);
        }

        float inv = 1.0f / (float)((end - beg) > 1 ? (end - beg) : 1);
        float4 xa = x4[n * 64 + lane * 2];
        float4 xb = x4[n * 64 + lane * 2 + 1];
        float d0 = xa.x - s0 * inv;
        float d1 = xa.y - s1 * inv;
        float d2 = xa.z - s2 * inv;
        float d3 = xa.w - s3 * inv;
        float d4 = xb.x - s4 * inv;
        float d5 = xb.y - s5 * inv;
        float d6 = xb.z - s6 * inv;
        float d7 = xb.w - s7 * inv;
        float local = fmaf(d0, d0, fmaf(d1, d1, fmaf(d2, d2, d3 * d3)))
                    + fmaf(d4, d4, fmaf(d5, d5, fmaf(d6, d6, d7 * d7)));
#pragma unroll
        for (int off = 16; off > 0; off >>= 1)
            local += __shfl_down_sync(0xFFFFFFFFu, local, off);

        __shared__ float fv8[8];
        if (lane == 0) {
            float fv = sqrtf(local);
            g_fvar[n] = fv;
            fv8[warp] = fv;
        }
        __syncthreads();
        if (t == 0) {
            float m = fv8[0];
#pragma unroll
            for (int w = 1; w < 8; w++) m = fmaxf(m, fv8[w]);
            atomicMax((int*)&g_max[2], __float_as_int(m));
        }
    }
}

// ---------------- K6: MLP with packed f32x2 FMA ----------------------------
__global__ void k_mlp(const float* __restrict__ w1, const float* __restrict__ b1,
                      const float* __restrict__ w2, const float* __restrict__ b2,
                      float* __restrict__ out) {
    __shared__ float feats[NPB][3];
    __shared__ __align__(16) float hid[HHALF][NPB];   // transposed: [j][node]
    int t = threadIdx.x;
    int n0 = blockIdx.x * NPB;

    if (t < NPB) {
        int n = n0 + t;
        float invd   = 1.0f / (g_max[0] + EPSV);
        float invden = 1.0f / (g_max[1] + EPSV);
        float invf   = 1.0f / (g_max[2] + EPSV);
        feats[t][0] = (float)g_deg[n] * invd;
        feats[t][1] = (g_density[n] - 1.0f) * invden;
        feats[t][2] = g_fvar[n] * invf;
    }
    __syncthreads();

    for (int idx = t; idx < NPB * HHALF; idx += 256) {
        int j = idx & (HHALF - 1);
        int node = idx >> 7;
        float v = b1[j]
                + feats[node][0] * w1[j]
                + feats[node][1] * w1[HHALF + j]
                + feats[node][2] * w1[2 * HHALF + j];
        hid[j][node] = fmaxf(v, 0.0f);
    }
    __syncthreads();

    // output layer: thread t owns column c = t; 16 packed accumulators = 32 nodes
    int c = t;
    unsigned long long acc[NPB / 2];
    float bc = b2[c];
    unsigned long long bcc = pk2(bc, bc);
#pragma unroll
    for (int p = 0; p < NPB / 2; p++) acc[p] = bcc;

    for (int j = 0; j < HHALF; j++) {
        float wj = w2[j * HID + c];
        unsigned long long wjj = pk2(wj, wj);
        const ulonglong2* hv = (const ulonglong2*)&hid[j][0];   // packed node pairs
#pragma unroll
        for (int q = 0; q < NPB / 4; q++) {
            ulonglong2 h2 = hv[q];                // 128-bit broadcast LDS
            fma2(acc[2 * q + 0], h2.x, wjj);
            fma2(acc[2 * q + 1], h2.y, wjj);
        }
    }
#pragma unroll
    for (int p = 0; p < NPB / 2; p++) {
        float2 v = upk(acc[p]);
        out[(n0 + 2 * p) * HID + c]     = v.x;
        out[(n0 + 2 * p + 1) * HID + c] = v.y;
    }
}

// ---------------- launch ----------------------------------------------------
extern "C" void kernel_launch(void* const* d_in, const int* in_sizes, int n_in,
                              void* d_out, int out_size) {
    const float*  x      = (const float*)d_in[0];
    const int*    ei     = (const int*)d_in[1];
    const float2* coords = (const float2*)d_in[2];
    const float*  w1     = (const float*)d_in[3];
    const float*  b1     = (const float*)d_in[4];
    const float*  w2     = (const float*)d_in[5];
    const float*  b2     = (const float*)d_in[6];
    float*        out    = (float*)d_out;

    const int* row = ei;
    const int* col = ei + N_EDGES;

    k_zero    <<<64, 256>>>();
    k_count   <<<64 + 2048 + 2048, 256>>>(coords, row, (const float4*)x);
    k_scans   <<<2, 1024>>>();
    k_fills   <<<64 + 256, 256>>>(coords, row, col);
    k_den_fvar<<<64 + 2048, 256>>>((const float4*)x);
    k_mlp     <<<N_NODES / NPB, 256>>>(w1, b1, w2, b2, out);
}

// round 9
// speedup vs baseline: 2.1537x; 1.0311x over previous
#include <cuda_runtime.h>
#include <cuda_bf16.h>

#define N_NODES 16384
#define N_EDGES 524288
#define HID 256
#define HHALF 128
#define R2 2500.0f
#define EPSV 1e-8f
#define NPB 32      // nodes per block in MLP kernel
#define GRIDC 20    // spatial grid cells per axis (cell = 50.0 = RADIUS)
#define NCELLS (GRIDC * GRIDC)

// ---------------- scratch (device globals: no allocation allowed) ----------
__device__ int    g_deg[N_NODES];
__device__ int    g_slot[N_EDGES];      // per-edge rank within its row
__device__ int    g_csr_ptr[N_NODES + 1];
__device__ int    g_csr_col[N_EDGES];
__device__ float  g_density[N_NODES];
__device__ float  g_fvar[N_NODES];
__device__ float  g_max[4];             // [0]=max deg, [1]=max(density-1), [2]=max fvar
__device__ unsigned int g_xh[N_NODES * HHALF];   // x in packed bf16x2, 8 MB
// spatial binning scratch
__device__ int    g_cell_cnt[NCELLS];
__device__ int    g_cell_fill[NCELLS];
__device__ int    g_cell_ptr[NCELLS + 1];
__device__ int    g_node_cell[N_NODES];
__device__ float2 g_sorted_xy[N_NODES];
__device__ int    g_sorted_id[N_NODES];

__device__ __forceinline__ int cell_of(float v) {
    int c = (int)(v * 0.02f);           // v / 50
    return min(max(c, 0), GRIDC - 1);
}

// pack two floats into one bf16x2 word: low 16 bits = first value
__device__ __forceinline__ unsigned int pack_bf(float lo, float hi) {
    unsigned int l = (unsigned int)__bfloat16_as_ushort(__float2bfloat16(lo));
    unsigned int h = (unsigned int)__bfloat16_as_ushort(__float2bfloat16(hi));
    return l | (h << 16);
}

// unpack bf16x2 word and accumulate into two f32 sums (2 ALU ops + 2 FADD)
__device__ __forceinline__ void bfacc(unsigned int u, float& a, float& b) {
    a += __uint_as_float(u << 16);
    b += __uint_as_float(u & 0xFFFF0000u);
}

// ---- packed f32x2 helpers (sm_103a: dual-lane FMA, full fp32 per lane) ----
__device__ __forceinline__ unsigned long long pk2(float a, float b) {
    unsigned long long r;
    asm("mov.b64 %0, {%1, %2};" : "=l"(r) : "f"(a), "f"(b));
    return r;
}
__device__ __forceinline__ void fma2(unsigned long long& d,
                                     unsigned long long a, unsigned long long b) {
    asm("fma.rn.f32x2 %0, %1, %2, %0;" : "+l"(d) : "l"(a), "l"(b));
}
__device__ __forceinline__ float2 upk(unsigned long long v) {
    float2 f;
    asm("mov.b64 {%0, %1}, %2;" : "=f"(f.x), "=f"(f.y) : "l"(v));
    return f;
}

// ---------------- K1: init --------------------------------------------------
__global__ void k_zero() {
    int i = blockIdx.x * blockDim.x + threadIdx.x;
    if (i < N_NODES) g_deg[i] = 0;
    if (i < NCELLS) { g_cell_cnt[i] = 0; g_cell_fill[i] = 0; }
    if (i < 4) g_max[i] = 0.0f;
}

// ---------------- K2: fused counts (bin hist || degree+slot || convert) ----
// blocks [0,64): node binning; [64,1088): degree 2 edges/thr; [1088,3136): convert
__global__ void k_count(const float2* __restrict__ coords, const int* __restrict__ row,
                        const float4* __restrict__ x4) {
    int b = blockIdx.x, t = threadIdx.x;
    if (b < 64) {
        int i = b * 256 + t;
        float2 p = coords[i];
        int c = cell_of(p.y) * GRIDC + cell_of(p.x);
        g_node_cell[i] = c;
        atomicAdd(&g_cell_cnt[c], 1);
    } else if (b < 64 + 1024) {
        int idx = (b - 64) * 256 + t;            // [0, 262144)
        int2 r2 = ((const int2*)row)[idx];
        int s0 = atomicAdd(&g_deg[r2.x], 1);
        int s1 = atomicAdd(&g_deg[r2.y], 1);
        ((int2*)g_slot)[idx] = make_int2(s0, s1);
    } else {
        // convert 8 floats -> 4 bf16x2 words per thread
        int idx = (b - 1088) * 256 + t;          // [0, 524288)
        float4 a = x4[2 * idx];
        float4 c = x4[2 * idx + 1];
        uint4 o;
        o.x = pack_bf(a.x, a.y);
        o.y = pack_bf(a.z, a.w);
        o.z = pack_bf(c.x, c.y);
        o.w = pack_bf(c.z, c.w);
        ((uint4*)g_xh)[idx] = o;
    }
}

// ---------------- K3: fused scans (shuffle-based) ---------------------------
__global__ void k_scans() {
    int t = threadIdx.x;
    int lane = t & 31, warp = t >> 5;
    if (blockIdx.x == 0) {
        // exclusive scan over 400 cell counts
        int v = (t < NCELLS) ? g_cell_cnt[t] : 0;
        int s = v;
#pragma unroll
        for (int o = 1; o < 32; o <<= 1) {
            int u = __shfl_up_sync(0xFFFFFFFFu, s, o);
            if (lane >= o) s += u;
        }
        __shared__ int wt[32];
        if (lane == 31) wt[warp] = s;
        __syncthreads();
        if (warp == 0) {
            int w = wt[lane];
#pragma unroll
            for (int o = 1; o < 32; o <<= 1) {
                int u = __shfl_up_sync(0xFFFFFFFFu, w, o);
                if (lane >= o) w += u;
            }
            wt[lane] = w;
        }
        __syncthreads();
        int incl = s + (warp > 0 ? wt[warp - 1] : 0);
        if (t < NCELLS) g_cell_ptr[t] = incl - v;
        if (t == NCELLS - 1) g_cell_ptr[NCELLS] = incl;
    } else {
        // exclusive scan over 16384 degrees + degree max
        int base = t * 16;
        int loc[16];
        int sum = 0, m = 0;
#pragma unroll
        for (int k = 0; k < 16; k++) {
            int d = g_deg[base + k];
            loc[k] = sum; sum += d; m = max(m, d);
        }
        int s = sum;
#pragma unroll
        for (int o = 1; o < 32; o <<= 1) {
            int u = __shfl_up_sync(0xFFFFFFFFu, s, o);
            if (lane >= o) s += u;
        }
#pragma unroll
        for (int o = 16; o > 0; o >>= 1)
            m = max(m, __shfl_down_sync(0xFFFFFFFFu, m, o));
        __shared__ int wt[32];
        __shared__ int wm[32];
        if (lane == 31) wt[warp] = s;
        if (lane == 0) wm[warp] = m;
        __syncthreads();
        if (warp == 0) {
            int w = wt[lane];
#pragma unroll
            for (int o = 1; o < 32; o <<= 1) {
                int u = __shfl_up_sync(0xFFFFFFFFu, w, o);
                if (lane >= o) w += u;
            }
            wt[lane] = w;
            int mm = wm[lane];
#pragma unroll
            for (int o = 16; o > 0; o >>= 1)
                mm = max(mm, __shfl_down_sync(0xFFFFFFFFu, mm, o));
            if (lane == 0) g_max[0] = (float)mm;
        }
        __syncthreads();
        int excl = s - sum + (warp > 0 ? wt[warp - 1] : 0);
#pragma unroll
        for (int k = 0; k < 16; k++) g_csr_ptr[base + k] = excl + loc[k];
        if (t == 1023) g_csr_ptr[N_NODES] = excl + sum;
    }
}

// ---------------- K4: fused fills (bin fill || CSR fill — NO atomics) ------
// blocks [0,64): bin fill; blocks [64, 64+1024): CSR fill, 2 edges/thread
__global__ void k_fills(const float2* __restrict__ coords,
                        const int* __restrict__ row, const int* __restrict__ col) {
    int b = blockIdx.x, t = threadIdx.x;
    if (b < 64) {
        int i = b * 256 + t;
        int c = g_node_cell[i];
        int pos = g_cell_ptr[c] + atomicAdd(&g_cell_fill[c], 1);
        g_sorted_xy[pos] = coords[i];
        g_sorted_id[pos] = i;
    } else {
        int idx = (b - 64) * 256 + t;          // idx in [0, 262144)
        int2 r2 = ((const int2*)row)[idx];
        int2 c2 = ((const int2*)col)[idx];
        int2 s2 = ((const int2*)g_slot)[idx];
        g_csr_col[g_csr_ptr[r2.x] + s2.x] = c2.x;
        g_csr_col[g_csr_ptr[r2.y] + s2.y] = c2.y;
    }
}

// ---------------- K5: fused density || fvar (bf16 gather, 8-deep MLP) ------
// blocks [0,64): density (1 node/thread); blocks [64, 64+2048): fvar (1 warp/node)
__global__ void k_den_fvar(const float4* __restrict__ x4) {
    int b = blockIdx.x, t = threadIdx.x;
    if (b < 64) {
        int i = b * 256 + t;
        float2 p = g_sorted_xy[i];
        int cx = cell_of(p.x), cy = cell_of(p.y);
        int y0 = max(cy - 1, 0), y1 = min(cy + 1, GRIDC - 1);
        int x0 = max(cx - 1, 0), x1 = min(cx + 1, GRIDC - 1);
        int cnt = 0;
        for (int yy = y0; yy <= y1; yy++) {
            int bb = g_cell_ptr[yy * GRIDC + x0];
            int ee = g_cell_ptr[yy * GRIDC + x1 + 1];
            for (int k = bb; k < ee; k++) {
                float2 q = g_sorted_xy[k];
                float dx = p.x - q.x;
                float dy = p.y - q.y;
                cnt += (fmaf(dx, dx, dy * dy) <= R2) ? 1 : 0;
            }
        }
        g_density[g_sorted_id[i]] = (float)cnt;
        float v = (float)(cnt - 1);
#pragma unroll
        for (int off = 16; off > 0; off >>= 1)
            v = fmaxf(v, __shfl_down_sync(0xFFFFFFFFu, v, off));
        __shared__ float wm[8];
        if ((t & 31) == 0) wm[t >> 5] = v;
        __syncthreads();
        if (t == 0) {
            float m = wm[0];
#pragma unroll
            for (int w = 1; w < 8; w++) m = fmaxf(m, wm[w]);
            atomicMax((int*)&g_max[1], __float_as_int(m));
        }
    } else {
        // -------- fvar: 1 warp per node, lane owns 8 features ----------
        int warp = t >> 5, lane = t & 31;
        int n = (b - 64) * 8 + warp;
        int beg = g_csr_ptr[n], end = g_csr_ptr[n + 1];
        const uint4* xh = (const uint4*)g_xh;   // [N_NODES * 32]

        float s0 = 0, s1 = 0, s2 = 0, s3 = 0, s4 = 0, s5 = 0, s6 = 0, s7 = 0;
        int e = beg;
        for (; e + 8 <= end; e += 8) {
            int cc[8];
#pragma unroll
            for (int k = 0; k < 8; k++) cc[k] = g_csr_col[e + k];
            uint4 vv[8];
#pragma unroll
            for (int k = 0; k < 8; k++) vv[k] = xh[cc[k] * 32 + lane];
#pragma unroll
            for (int k = 0; k < 8; k++) {
                bfacc(vv[k].x, s0, s1); bfacc(vv[k].y, s2, s3);
                bfacc(vv[k].z, s4, s5); bfacc(vv[k].w, s6, s7);
            }
        }
        for (; e < end; e++) {
            uint4 v = xh[g_csr_col[e] * 32 + lane];
            bfacc(v.x, s0, s1); bfacc(v.y, s2, s3); bfacc(v.z, s4, s5); bfacc(v.w, s6, s7);
        }

        float inv = 1.0f / (float)((end - beg) > 1 ? (end - beg) : 1);
        float4 xa = x4[n * 64 + lane * 2];
        float4 xb = x4[n * 64 + lane * 2 + 1];
        float d0 = xa.x - s0 * inv;
        float d1 = xa.y - s1 * inv;
        float d2 = xa.z - s2 * inv;
        float d3 = xa.w - s3 * inv;
        float d4 = xb.x - s4 * inv;
        float d5 = xb.y - s5 * inv;
        float d6 = xb.z - s6 * inv;
        float d7 = xb.w - s7 * inv;
        float local = fmaf(d0, d0, fmaf(d1, d1, fmaf(d2, d2, d3 * d3)))
                    + fmaf(d4, d4, fmaf(d5, d5, fmaf(d6, d6, d7 * d7)));
#pragma unroll
        for (int off = 16; off > 0; off >>= 1)
            local += __shfl_down_sync(0xFFFFFFFFu, local, off);

        __shared__ float fv8[8];
        if (lane == 0) {
            float fv = sqrtf(local);
            g_fvar[n] = fv;
            fv8[warp] = fv;
        }
        __syncthreads();
        if (t == 0) {
            float m = fv8[0];
#pragma unroll
            for (int w = 1; w < 8; w++) m = fmaxf(m, fv8[w]);
            atomicMax((int*)&g_max[2], __float_as_int(m));
        }
    }
}

// ---------------- K6: MLP with packed f32x2 FMA ----------------------------
__global__ void k_mlp(const float* __restrict__ w1, const float* __restrict__ b1,
                      const float* __restrict__ w2, const float* __restrict__ b2,
                      float* __restrict__ out) {
    __shared__ float feats[NPB][3];
    __shared__ __align__(16) float hid[HHALF][NPB];   // transposed: [j][node]
    int t = threadIdx.x;
    int n0 = blockIdx.x * NPB;

    if (t < NPB) {
        int n = n0 + t;
        float invd   = 1.0f / (g_max[0] + EPSV);
        float invden = 1.0f / (g_max[1] + EPSV);
        float invf   = 1.0f / (g_max[2] + EPSV);
        feats[t][0] = (float)g_deg[n] * invd;
        feats[t][1] = (g_density[n] - 1.0f) * invden;
        feats[t][2] = g_fvar[n] * invf;
    }
    __syncthreads();

    for (int idx = t; idx < NPB * HHALF; idx += 256) {
        int j = idx & (HHALF - 1);
        int node = idx >> 7;
        float v = b1[j]
                + feats[node][0] * w1[j]
                + feats[node][1] * w1[HHALF + j]
                + feats[node][2] * w1[2 * HHALF + j];
        hid[j][node] = fmaxf(v, 0.0f);
    }
    __syncthreads();

    // output layer: thread t owns column c = t; 16 packed accumulators = 32 nodes
    int c = t;
    unsigned long long acc[NPB / 2];
    float bc = b2[c];
    unsigned long long bcc = pk2(bc, bc);
#pragma unroll
    for (int p = 0; p < NPB / 2; p++) acc[p] = bcc;

    for (int j = 0; j < HHALF; j++) {
        float wj = w2[j * HID + c];
        unsigned long long wjj = pk2(wj, wj);
        const ulonglong2* hv = (const ulonglong2*)&hid[j][0];   // packed node pairs
#pragma unroll
        for (int q = 0; q < NPB / 4; q++) {
            ulonglong2 h2 = hv[q];                // 128-bit broadcast LDS
            fma2(acc[2 * q + 0], h2.x, wjj);
            fma2(acc[2 * q + 1], h2.y, wjj);
        }
    }
#pragma unroll
    for (int p = 0; p < NPB / 2; p++) {
        float2 v = upk(acc[p]);
        out[(n0 + 2 * p) * HID + c]     = v.x;
        out[(n0 + 2 * p + 1) * HID + c] = v.y;
    }
}

// ---------------- launch ----------------------------------------------------
extern "C" void kernel_launch(void* const* d_in, const int* in_sizes, int n_in,
                              void* d_out, int out_size) {
    const float*  x      = (const float*)d_in[0];
    const int*    ei     = (const int*)d_in[1];
    const float2* coords = (const float2*)d_in[2];
    const float*  w1     = (const float*)d_in[3];
    const float*  b1     = (const float*)d_in[4];
    const float*  w2     = (const float*)d_in[5];
    const float*  b2     = (const float*)d_in[6];
    float*        out    = (float*)d_out;

    const int* row = ei;
    const int* col = ei + N_EDGES;

    k_zero    <<<64, 256>>>();
    k_count   <<<64 + 1024 + 2048, 256>>>(coords, row, (const float4*)x);
    k_scans   <<<2, 1024>>>();
    k_fills   <<<64 + 1024, 256>>>(coords, row, col);
    k_den_fvar<<<64 + 2048, 256>>>((const float4*)x);
    k_mlp     <<<N_NODES / NPB, 256>>>(w1, b1, w2, b2, out);
}